// round 5
// baseline (speedup 1.0000x reference)
#include <cuda_runtime.h>

// Laplacian_22711787061657
// x: (32, 1, 1024, 1024) fp32. Circular 2nd difference along H and W:
//   gx[h][w] = x[h-2][w] - 2*x[h-1][w] + x[h][w]   (mod 1024)
//   gy[h][w] = x[h][w-2] - 2*x[h][w-1] + x[h][w]   (mod 1024)
//   out = clip(gx+gy, -1, 1) * 0.5, NaN(x)->1.0 on input, NaN->0 on output.
//
// v5 = v4 (proven inner loop: two float4 loads + plain store, CHUNK=32,
// grid 1024) with the occupancy cap lifted and deeper unroll:
//   - __launch_bounds__(256, 6): regs capped ~42 -> 6 CTAs/SM (48 warps, 75%
//     occ) instead of 4 (32 warps). We are MLP/latency-exposed at 70% DRAM;
//     +50% resident warps -> more outstanding misses.
//   - unroll 8: 16 batched loads per warp between dependency stalls.

#define HW 1024           // H == W == 1024
#define ROW_F4 (HW / 4)   // 256 float4 per row
#define CHUNK 32          // rows per block
#define NCHUNK (HW / CHUNK)

__device__ __forceinline__ float4 scrub1(float4 v) {
    // remove_nan(x, 1.0)
    v.x = isnan(v.x) ? 1.0f : v.x;
    v.y = isnan(v.y) ? 1.0f : v.y;
    v.z = isnan(v.z) ? 1.0f : v.z;
    v.w = isnan(v.w) ? 1.0f : v.w;
    return v;
}

__device__ __forceinline__ float finish(float gx, float gy) {
    // 0.5 * clip(gx+gy, -1, 1) == clamp(0.5*(gx+gy), -0.5, 0.5)
    float g = 0.5f * (gx + gy);
    g = fminf(0.5f, fmaxf(-0.5f, g));
    return isnan(g) ? 0.0f : g;   // remove_nan on output
}

__global__ __launch_bounds__(ROW_F4, 6)
void laplacian_kernel(const float4* __restrict__ x, float4* __restrict__ out) {
    const int t     = threadIdx.x;        // column float4 index, 0..255
    const int chunk = blockIdx.x;         // 0..NCHUNK-1
    const int b     = blockIdx.y;         // image index

    const size_t img_off = (size_t)b * (HW * ROW_F4);
    const float4* __restrict__ xi = x + img_off;
    float4* __restrict__ oi = out + img_off;

    const int tp = (t + ROW_F4 - 1) & (ROW_F4 - 1); // float4 at w-4 (circular)

    const int h0  = chunk * CHUNK;
    const int hm2 = (h0 + HW - 2) & (HW - 1);
    const int hm1 = (h0 + HW - 1) & (HW - 1);

    float4 rm2 = scrub1(xi[(size_t)hm2 * ROW_F4 + t]); // row h-2
    float4 rm1 = scrub1(xi[(size_t)hm1 * ROW_F4 + t]); // row h-1

    const float4* __restrict__ rin  = xi + (size_t)h0 * ROW_F4;
    float4*       __restrict__ rout = oi + (size_t)h0 * ROW_F4;

    #pragma unroll 8
    for (int i = 0; i < CHUNK; ++i) {
        const float4 a = scrub1(rin[t]);    // row h, elems 4t..4t+3
        const float4 p = scrub1(rin[tp]);   // row h, elems 4t-4..4t-1 (L1 hit)

        float4 g;
        g.x = finish(rm2.x - 2.0f * rm1.x + a.x,  p.z - 2.0f * p.w + a.x);
        g.y = finish(rm2.y - 2.0f * rm1.y + a.y,  p.w - 2.0f * a.x + a.y);
        g.z = finish(rm2.z - 2.0f * rm1.z + a.z,  a.x - 2.0f * a.y + a.z);
        g.w = finish(rm2.w - 2.0f * rm1.w + a.w,  a.y - 2.0f * a.z + a.w);

        rout[t] = g;

        rm2 = rm1;
        rm1 = a;
        rin  += ROW_F4;
        rout += ROW_F4;
    }
}

extern "C" void kernel_launch(void* const* d_in, const int* in_sizes, int n_in,
                              void* d_out, int out_size) {
    const float4* x = (const float4*)d_in[0];
    float4* out = (float4*)d_out;
    const int batch = in_sizes[0] / (HW * HW); // 32

    dim3 grid(NCHUNK, batch);
    dim3 block(ROW_F4);
    laplacian_kernel<<<grid, block>>>(x, out);
}

// round 6
// speedup vs baseline: 1.0269x; 1.0269x over previous
#include <cuda_runtime.h>

// Laplacian_22711787061657
// x: (32, 1, 1024, 1024) fp32. Circular 2nd difference along H and W:
//   gx[h][w] = x[h-2][w] - 2*x[h-1][w] + x[h][w]   (mod 1024)
//   gy[h][w] = x[h][w-2] - 2*x[h][w-1] + x[h][w]   (mod 1024)
//   out = clip(gx+gy, -1, 1) * 0.5, NaN(x)->1.0 on input, NaN->0 on output.
//
// v6: dual rolling chains per thread. R5 proved more warps hurt (L1tex queue
// contention); the limiter is per-warp MLP at the 4-CTA/SM budget. Each
// block owns 64 rows; each thread walks TWO independent row chains
// (h0+i and h0+32+i), front-batching 4 independent float4 loads per
// iteration instead of 2. Same DRAM traffic as v4, double the in-flight
// misses per warp, no occupancy change. lb(256,4) keeps the 64-reg budget.

#define HW 1024           // H == W == 1024
#define ROW_F4 (HW / 4)   // 256 float4 per row
#define CHUNK 64          // rows per block (two 32-row chains)
#define HALF  32
#define NCHUNK (HW / CHUNK)

__device__ __forceinline__ float4 scrub1(float4 v) {
    // remove_nan(x, 1.0)
    v.x = isnan(v.x) ? 1.0f : v.x;
    v.y = isnan(v.y) ? 1.0f : v.y;
    v.z = isnan(v.z) ? 1.0f : v.z;
    v.w = isnan(v.w) ? 1.0f : v.w;
    return v;
}

__device__ __forceinline__ float finish(float gx, float gy) {
    // 0.5 * clip(gx+gy, -1, 1) == clamp(0.5*(gx+gy), -0.5, 0.5)
    float g = 0.5f * (gx + gy);
    g = fminf(0.5f, fmaxf(-0.5f, g));
    return isnan(g) ? 0.0f : g;   // remove_nan on output
}

__device__ __forceinline__ float4 lap4(const float4 rm2, const float4 rm1,
                                       const float4 a, const float4 p) {
    float4 g;
    g.x = finish(rm2.x - 2.0f * rm1.x + a.x,  p.z - 2.0f * p.w + a.x);
    g.y = finish(rm2.y - 2.0f * rm1.y + a.y,  p.w - 2.0f * a.x + a.y);
    g.z = finish(rm2.z - 2.0f * rm1.z + a.z,  a.x - 2.0f * a.y + a.z);
    g.w = finish(rm2.w - 2.0f * rm1.w + a.w,  a.y - 2.0f * a.z + a.w);
    return g;
}

__global__ __launch_bounds__(ROW_F4, 4)
void laplacian_kernel(const float4* __restrict__ x, float4* __restrict__ out) {
    const int t     = threadIdx.x;        // column float4 index, 0..255
    const int chunk = blockIdx.x;         // 0..NCHUNK-1
    const int b     = blockIdx.y;         // image index

    const size_t img_off = (size_t)b * (HW * ROW_F4);
    const float4* __restrict__ xi = x + img_off;
    float4* __restrict__ oi = out + img_off;

    const int tp = (t + ROW_F4 - 1) & (ROW_F4 - 1); // float4 at w-4 (circular)

    const int h0 = chunk * CHUNK;         // chain A: rows h0..h0+31
    const int h1 = h0 + HALF;             // chain B: rows h1..h1+63... h1+31

    // Preload the two rows above each chain start (circular for chain A).
    const int am2 = (h0 + HW - 2) & (HW - 1);
    const int am1 = (h0 + HW - 1) & (HW - 1);

    float4 rm2A = scrub1(xi[(size_t)am2 * ROW_F4 + t]);
    float4 rm1A = scrub1(xi[(size_t)am1 * ROW_F4 + t]);
    float4 rm2B = scrub1(xi[(size_t)(h1 - 2) * ROW_F4 + t]);
    float4 rm1B = scrub1(xi[(size_t)(h1 - 1) * ROW_F4 + t]);

    const float4* __restrict__ rinA  = xi + (size_t)h0 * ROW_F4;
    float4*       __restrict__ routA = oi + (size_t)h0 * ROW_F4;
    const float4* __restrict__ rinB  = xi + (size_t)h1 * ROW_F4;
    float4*       __restrict__ routB = oi + (size_t)h1 * ROW_F4;

    #pragma unroll 2
    for (int i = 0; i < HALF; ++i) {
        // Batch all 4 independent loads first (max MLP per warp).
        const float4 aA = scrub1(rinA[t]);
        const float4 pA = scrub1(rinA[tp]);
        const float4 aB = scrub1(rinB[t]);
        const float4 pB = scrub1(rinB[tp]);

        routA[t] = lap4(rm2A, rm1A, aA, pA);
        routB[t] = lap4(rm2B, rm1B, aB, pB);

        rm2A = rm1A;  rm1A = aA;
        rm2B = rm1B;  rm1B = aB;
        rinA += ROW_F4;  routA += ROW_F4;
        rinB += ROW_F4;  routB += ROW_F4;
    }
}

extern "C" void kernel_launch(void* const* d_in, const int* in_sizes, int n_in,
                              void* d_out, int out_size) {
    const float4* x = (const float4*)d_in[0];
    float4* out = (float4*)d_out;
    const int batch = in_sizes[0] / (HW * HW); // 32

    dim3 grid(NCHUNK, batch);
    dim3 block(ROW_F4);
    laplacian_kernel<<<grid, block>>>(x, out);
}

// round 7
// speedup vs baseline: 1.0630x; 1.0352x over previous
#include <cuda_runtime.h>

// Laplacian_22711787061657
// x: (32, 1, 1024, 1024) fp32. Circular 2nd difference along H and W:
//   gx[h][w] = x[h-2][w] - 2*x[h-1][w] + x[h][w]   (mod 1024)
//   gy[h][w] = x[h][w-2] - 2*x[h][w-1] + x[h][w]   (mod 1024)
//   out = clip(gx+gy, -1, 1) * 0.5, NaN(x)->1.0 on input, NaN->0 on output.
//
// v7 = v4 verbatim (proven-best structure: rolling H registers, full float4
// p-load, CHUNK=32, grid 1024, lb(256,4)) + __stcs on the output store ONLY.
// Rationale: graph replays reuse the same 134 MB input; L2 is 126 MB. ncu
// shows ~227 MB DRAM traffic vs 268 MB naive -> input partially L2-resident
// across replays already. Evict-first output stores stop the write stream
// from evicting input lines, raising cross-replay input hit rate.
// (R3 tested stcs confounded with a serialized 8B load; this is the clean test.)

#define HW 1024           // H == W == 1024
#define ROW_F4 (HW / 4)   // 256 float4 per row
#define CHUNK 32          // rows per block
#define NCHUNK (HW / CHUNK)

__device__ __forceinline__ float4 scrub1(float4 v) {
    // remove_nan(x, 1.0)
    v.x = isnan(v.x) ? 1.0f : v.x;
    v.y = isnan(v.y) ? 1.0f : v.y;
    v.z = isnan(v.z) ? 1.0f : v.z;
    v.w = isnan(v.w) ? 1.0f : v.w;
    return v;
}

__device__ __forceinline__ float finish(float gx, float gy) {
    // 0.5 * clip(gx+gy, -1, 1) == clamp(0.5*(gx+gy), -0.5, 0.5)
    float g = 0.5f * (gx + gy);
    g = fminf(0.5f, fmaxf(-0.5f, g));
    return isnan(g) ? 0.0f : g;   // remove_nan on output
}

__global__ __launch_bounds__(ROW_F4, 4)
void laplacian_kernel(const float4* __restrict__ x, float4* __restrict__ out) {
    const int t     = threadIdx.x;        // column float4 index, 0..255
    const int chunk = blockIdx.x;         // 0..NCHUNK-1
    const int b     = blockIdx.y;         // image index

    const size_t img_off = (size_t)b * (HW * ROW_F4);
    const float4* __restrict__ xi = x + img_off;
    float4* __restrict__ oi = out + img_off;

    const int tp = (t + ROW_F4 - 1) & (ROW_F4 - 1); // float4 at w-4 (circular)

    const int h0  = chunk * CHUNK;
    const int hm2 = (h0 + HW - 2) & (HW - 1);
    const int hm1 = (h0 + HW - 1) & (HW - 1);

    float4 rm2 = scrub1(xi[(size_t)hm2 * ROW_F4 + t]); // row h-2
    float4 rm1 = scrub1(xi[(size_t)hm1 * ROW_F4 + t]); // row h-1

    const float4* __restrict__ rin  = xi + (size_t)h0 * ROW_F4;
    float4*       __restrict__ rout = oi + (size_t)h0 * ROW_F4;

    #pragma unroll 4
    for (int i = 0; i < CHUNK; ++i) {
        const float4 a = scrub1(rin[t]);    // row h, elems 4t..4t+3
        const float4 p = scrub1(rin[tp]);   // row h, elems 4t-4..4t-1 (L1 hit)

        float4 g;
        g.x = finish(rm2.x - 2.0f * rm1.x + a.x,  p.z - 2.0f * p.w + a.x);
        g.y = finish(rm2.y - 2.0f * rm1.y + a.y,  p.w - 2.0f * a.x + a.y);
        g.z = finish(rm2.z - 2.0f * rm1.z + a.z,  a.x - 2.0f * a.y + a.z);
        g.w = finish(rm2.w - 2.0f * rm1.w + a.w,  a.y - 2.0f * a.z + a.w);

        __stcs(rout + t, g);   // streaming store: keep the input resident in L2

        rm2 = rm1;
        rm1 = a;
        rin  += ROW_F4;
        rout += ROW_F4;
    }
}

extern "C" void kernel_launch(void* const* d_in, const int* in_sizes, int n_in,
                              void* d_out, int out_size) {
    const float4* x = (const float4*)d_in[0];
    float4* out = (float4*)d_out;
    const int batch = in_sizes[0] / (HW * HW); // 32

    dim3 grid(NCHUNK, batch);
    dim3 block(ROW_F4);
    laplacian_kernel<<<grid, block>>>(x, out);
}